// round 7
// baseline (speedup 1.0000x reference)
#include <cuda_runtime.h>
#include <cuda_fp16.h>
#include <cstdint>

#define HH 256
#define WW 256
#define NB 8
#define PLANE (HH*WW)
#define CIN 256
#define CHID 16

// per-sample demodulated conv weights, fp16 half2-packed: [b][tap][o][32 words]
__device__ unsigned g_wmodh[NB * 9 * 64 * 32];
// normalized activations, fp16 half2-packed pixel-major: [b][pix][32 words]
__device__ unsigned g_nx[(size_t)NB * PLANE * 32];

// ---------------------------------------------------------------------------
// Kernel 1: style MLP + weight modulation/demodulation -> fp16 packed weights
// ---------------------------------------------------------------------------
__global__ void style_kernel(const float* __restrict__ vec,
                             const float* __restrict__ w1,
                             const float* __restrict__ w2,
                             const float* __restrict__ wconv) {
    const int b = blockIdx.x, tid = threadIdx.x;
    __shared__ float sv[CIN], sh[CHID], ss[64];
    sv[tid] = vec[b*CIN + tid];
    __syncthreads();
    if (tid < CHID) {
        float acc = 0.f;
        #pragma unroll 8
        for (int c = 0; c < CIN; ++c) acc += sv[c] * w1[tid*CIN + c];
        sh[tid] = (acc > 0.f) ? acc : 0.1f * acc;     // LeakyReLU(0.1)
    }
    __syncthreads();
    if (tid < 64) {
        float acc = 0.f;
        #pragma unroll
        for (int j = 0; j < CHID; ++j) acc += sh[j] * w2[tid*CHID + j];
        ss[tid] = acc + 1.0f;                          // sty + 1
    }
    __syncthreads();
    const int warp = tid >> 5, lane = tid & 31;
    for (int o = warp; o < 64; o += 8) {
        float acc = 0.f;
        for (int idx = lane; idx < 576; idx += 32) {
            float v = wconv[o*576 + idx] * ss[idx / 9];
            acc += v * v;
        }
        #pragma unroll
        for (int s = 16; s; s >>= 1) acc += __shfl_xor_sync(0xffffffffu, acc, s);
        const float d = rsqrtf(acc + 1e-8f);
        for (int m = lane; m < 288; m += 32) {
            const int ip = m / 9, t = m % 9;
            const int i0 = 2 * ip;
            float v0 = wconv[o*576 + i0*9 + t]     * ss[i0]   * d;
            float v1 = wconv[o*576 + (i0+1)*9 + t] * ss[i0+1] * d;
            __half2 h = __floats2half2_rn(v0, v1);
            g_wmodh[(size_t)((b*9 + t)*64 + o)*32 + ip] = *(unsigned*)&h;
        }
    }
}

// ---------------------------------------------------------------------------
// Kernel 1b: ChanNorm -> fp16 pixel-major tensor (streaming, fully coalesced)
// Block = 256 consecutive pixels; XOR-swizzled smem transpose for stores.
// ---------------------------------------------------------------------------
__global__ __launch_bounds__(256)
void norm_kernel(const float* __restrict__ x,
                 const float* __restrict__ gaff,
                 const float* __restrict__ baff) {
    __shared__ unsigned st[256 * 32];                  // 32 KB
    __shared__ float sg[64], sb[64];
    const int tid = threadIdx.x, blk = blockIdx.x, b = blockIdx.y;
    if (tid < 64) { sg[tid] = gaff[tid]; sb[tid] = baff[tid]; }
    __syncthreads();

    const int p0 = blk * 256;
    const float* xb = x + (size_t)b * 64 * PLANE + p0;

    float v[64], s = 0.f, s2 = 0.f;
    #pragma unroll
    for (int c = 0; c < 64; ++c) v[c] = xb[(size_t)c * PLANE + tid];
    #pragma unroll
    for (int c = 0; c < 64; ++c) { s += v[c]; s2 += v[c]*v[c]; }
    const float mean = s * (1.f/64.f);
    const float rstd = rsqrtf(s2 * (1.f/64.f) - mean*mean + 1e-5f);

    // pack to fp16, store to smem with chunk XOR swizzle (conflict-free)
    #pragma unroll
    for (int u = 0; u < 8; ++u) {                      // u = 16B chunk
        unsigned w[4];
        #pragma unroll
        for (int q = 0; q < 4; ++q) {
            const int c0 = u*8 + q*2;
            float n0 = (v[c0]   - mean) * rstd * sg[c0]   + sb[c0];
            float n1 = (v[c0+1] - mean) * rstd * sg[c0+1] + sb[c0+1];
            __half2 h = __floats2half2_rn(n0, n1);
            w[q] = *(unsigned*)&h;
        }
        const int cs = u ^ (tid & 7);
        *(uint4*)&st[tid*32 + cs*4] = *(uint4*)w;
    }
    __syncthreads();

    // coalesced 16B stores to g_nx
    uint4* g4 = (uint4*)g_nx + ((size_t)b * PLANE + p0) * 8;
    #pragma unroll
    for (int i = 0; i < 8; ++i) {
        const int gidx = i*256 + tid;                  // global uint4 within block
        const int pix = gidx >> 3, w4 = gidx & 7;
        const int cs = w4 ^ (pix & 7);
        g4[gidx] = *(const uint4*)&st[pix*32 + cs*4];
    }
}

// ---------------------------------------------------------------------------
// Kernel 2: 3x3 modulated conv (fp16 m16n8k16 + ldmatrix) + residual.
// CTA = 8 rows x 64 cols x 64 out-ch; 8 warps, warp = one row (Mw=64,Nw=64).
// Halo loaded via cp.async from the pre-normalized fp16 tensor.
// xs: [pix = r*66+cc][36 words]; wt: double buffer [2][64][36 words].
// ---------------------------------------------------------------------------
#define XW 36
#define HROWS 10
#define HCOLS 66
#define NPX (HROWS*HCOLS)                 /* 660 halo pixels */
#define OFF_WT (NPX*XW)                   /* 23760 words */
#define WTBUF  (64*XW)                    /* 2304 words per buffer */
#define SMEM_WORDS (OFF_WT + 2*WTBUF)     /* 28368 words = 113472 B */

__device__ __forceinline__ uint32_t smem_u32(const void* p) {
    uint32_t a;
    asm("{ .reg .u64 t; cvta.to.shared.u64 t, %1; cvt.u32.u64 %0, t; }" : "=r"(a) : "l"(p));
    return a;
}
__device__ __forceinline__ void ldsm_x4(unsigned r[4], uint32_t addr) {
    asm volatile("ldmatrix.sync.aligned.m8n8.x4.shared.b16 {%0,%1,%2,%3}, [%4];"
        : "=r"(r[0]), "=r"(r[1]), "=r"(r[2]), "=r"(r[3]) : "r"(addr));
}
__device__ __forceinline__ void mma_f16(float c[4],
                                        unsigned a0, unsigned a1,
                                        unsigned a2, unsigned a3,
                                        unsigned b0, unsigned b1) {
    asm volatile(
        "mma.sync.aligned.m16n8k16.row.col.f32.f16.f16.f32 "
        "{%0,%1,%2,%3}, {%4,%5,%6,%7}, {%8,%9}, {%0,%1,%2,%3};\n"
        : "+f"(c[0]), "+f"(c[1]), "+f"(c[2]), "+f"(c[3])
        : "r"(a0), "r"(a1), "r"(a2), "r"(a3), "r"(b0), "r"(b1));
}
__device__ __forceinline__ void cp16(uint32_t dst, const void* src, int sz) {
    asm volatile("cp.async.ca.shared.global [%0], [%1], 16, %2;"
        :: "r"(dst), "l"(src), "r"(sz) : "memory");
}

__global__ __launch_bounds__(256, 1)
void conv_kernel(const float* __restrict__ x,
                 float* __restrict__ out) {
    extern __shared__ unsigned sm[];
    const int tid = threadIdx.x, warp = tid >> 5, lane = tid & 31;
    const int gq = lane >> 2, tq = lane & 3;
    const int x0 = blockIdx.x * 64, y0 = blockIdx.y * 8, b = blockIdx.z;
    const float* xb = x + (size_t)b * 64 * PLANE;
    const uint32_t xs_sa = smem_u32(sm);
    const uint32_t wt_sa = xs_sa + OFF_WT * 4;

    // ---- cp.async halo fill (zero-fill out-of-range via src_size=0) ----
    const uint4* nxb = (const uint4*)g_nx + (size_t)b * PLANE * 8;
    for (int q = tid; q < NPX * 8; q += 256) {
        const int p = q >> 3, ch = q & 7;
        const int r = p / HCOLS, cc = p % HCOLS;
        const int gy = y0 - 1 + r, gx = x0 - 1 + cc;
        const bool ok = (gy >= 0) & (gy < HH) & (gx >= 0) & (gx < WW);
        const uint4* src = nxb + ((size_t)(ok ? gy*WW + gx : 0)) * 8 + ch;
        cp16(xs_sa + (uint32_t)(p*XW + ch*4) * 4, src, ok ? 16 : 0);
    }
    asm volatile("cp.async.commit_group;" ::: "memory");

    // ---- weight prefetch: tap0 -> wt buf0, tap1 -> regs ----
    const unsigned* wbase = g_wmodh + (size_t)(b * 9) * 2048;
    const int wdo = (tid >> 2) * XW + (tid & 3) * 8;   // dst word offset in tile
    uint4 wr[2];
    {
        const uint4* s4 = (const uint4*)wbase + tid * 2;
        wr[0] = s4[0]; wr[1] = s4[1];
        uint4* d = (uint4*)(sm + OFF_WT + wdo);
        d[0] = wr[0]; d[1] = wr[1];
        const uint4* s4b = (const uint4*)(wbase + 2048) + tid * 2;
        wr[0] = s4b[0]; wr[1] = s4b[1];
    }

    // ---- ldmatrix base addresses ----
    const uint32_t A0 = xs_sa + (uint32_t)((warp * HCOLS + (lane & 15)) * XW) * 4
                              + (uint32_t)(lane >> 4) * 16;
    const uint32_t B0 = wt_sa + (uint32_t)((((lane & 7) + ((lane >> 4) & 1) * 8)) * XW) * 4
                              + (uint32_t)((lane >> 3) & 1) * 16;

    asm volatile("cp.async.wait_group 0;" ::: "memory");
    __syncthreads();                                   // xs + wt0 ready

    float acc[4][8][4];
    #pragma unroll
    for (int mt = 0; mt < 4; ++mt)
        #pragma unroll
        for (int nt = 0; nt < 8; ++nt)
            #pragma unroll
            for (int j = 0; j < 4; ++j) acc[mt][nt][j] = 0.f;

    for (int j = 0; j < 9; ++j) {
        const int ky = j / 3, kx = j % 3, s = j & 1;
        const uint32_t Abase = A0 + (uint32_t)((ky * HCOLS + kx) * XW) * 4;
        const uint32_t Bbase = B0 + (uint32_t)(s * WTBUF) * 4;

        unsigned a[2][4][4], bq[2][4][4];
        #pragma unroll
        for (int mt = 0; mt < 4; ++mt)
            ldsm_x4(a[0][mt], Abase + (uint32_t)(mt * 16 * XW) * 4);
        #pragma unroll
        for (int q = 0; q < 4; ++q)
            ldsm_x4(bq[0][q], Bbase + (uint32_t)(q * 16 * XW) * 4);

        #pragma unroll
        for (int kt = 0; kt < 4; ++kt) {
            const int cur = kt & 1, nxt = cur ^ 1;
            if (kt < 3) {
                const uint32_t ko = (uint32_t)(kt + 1) * 32;
                #pragma unroll
                for (int mt = 0; mt < 4; ++mt)
                    ldsm_x4(a[nxt][mt], Abase + (uint32_t)(mt * 16 * XW) * 4 + ko);
                #pragma unroll
                for (int q = 0; q < 4; ++q)
                    ldsm_x4(bq[nxt][q], Bbase + (uint32_t)(q * 16 * XW) * 4 + ko);
            }
            #pragma unroll
            for (int mt = 0; mt < 4; ++mt) {
                #pragma unroll
                for (int q = 0; q < 4; ++q) {
                    mma_f16(acc[mt][2*q],   a[cur][mt][0], a[cur][mt][1],
                            a[cur][mt][2], a[cur][mt][3],
                            bq[cur][q][0], bq[cur][q][1]);
                    mma_f16(acc[mt][2*q+1], a[cur][mt][0], a[cur][mt][1],
                            a[cur][mt][2], a[cur][mt][3],
                            bq[cur][q][2], bq[cur][q][3]);
                }
            }
        }

        if (j < 8) {
            uint4* d = (uint4*)(sm + OFF_WT + (s ^ 1) * WTBUF + wdo);
            d[0] = wr[0]; d[1] = wr[1];
            if (j < 7) {
                const uint4* s4 = (const uint4*)(wbase + (size_t)(j+2)*2048) + tid*2;
                wr[0] = s4[0]; wr[1] = s4[1];
            }
        }
        __syncthreads();
    }

    // ---- epilogue: per-warp smem staging, coalesced residual + store ----
    float* ss = (float*)sm + warp * 2112;              // 32ch x 66 floats/warp
    const int gy = y0 + warp;
    float* ob = out + (size_t)b * 64 * PLANE;

    #pragma unroll
    for (int P = 0; P < 2; ++P) {
        #pragma unroll
        for (int mt = 0; mt < 4; ++mt) {
            const int px = mt*16 + gq;
            #pragma unroll
            for (int ntl = 0; ntl < 4; ++ntl) {
                const int nt = P*4 + ntl;
                const int c = ntl*8 + 2*tq;
                ss[c*66 + px]         = acc[mt][nt][0];
                ss[(c+1)*66 + px]     = acc[mt][nt][1];
                ss[c*66 + px + 8]     = acc[mt][nt][2];
                ss[(c+1)*66 + px + 8] = acc[mt][nt][3];
            }
        }
        __syncwarp();
        #pragma unroll 4
        for (int c = 0; c < 32; ++c) {
            const int cg = P*32 + c;
            const size_t gi = (size_t)cg * PLANE + (size_t)gy * WW + x0 + 2*lane;
            const float2 v = *(const float2*)&ss[c*66 + 2*lane];
            const float2 rx = *(const float2*)&xb[gi];
            float2 o2; o2.x = v.x + rx.x; o2.y = v.y + rx.y;
            *(float2*)&ob[gi] = o2;
        }
        __syncwarp();
    }
}

// ---------------------------------------------------------------------------
extern "C" void kernel_launch(void* const* d_in, const int* in_sizes, int n_in,
                              void* d_out, int out_size) {
    (void)in_sizes; (void)n_in; (void)out_size;
    const float* x     = (const float*)d_in[0];
    const float* vec   = (const float*)d_in[1];
    const float* gaff  = (const float*)d_in[2];
    const float* baff  = (const float*)d_in[3];
    const float* w1    = (const float*)d_in[4];
    const float* w2    = (const float*)d_in[5];
    const float* wconv = (const float*)d_in[6];
    float* out = (float*)d_out;

    style_kernel<<<NB, 256>>>(vec, w1, w2, wconv);

    dim3 ngrid(PLANE/256, NB);
    norm_kernel<<<ngrid, 256>>>(x, gaff, baff);

    const int smem = SMEM_WORDS * 4;
    cudaFuncSetAttribute(conv_kernel,
                         cudaFuncAttributeMaxDynamicSharedMemorySize, smem);
    dim3 grid(WW/64, HH/8, NB);
    conv_kernel<<<grid, 256, smem>>>(x, out);
}

// round 8
// speedup vs baseline: 1.5199x; 1.5199x over previous
#include <cuda_runtime.h>
#include <cuda_fp16.h>
#include <cstdint>

#define HH 256
#define WW 256
#define NB 8
#define PLANE (HH*WW)
#define CIN 256
#define CHID 16

// per-sample demodulated conv weights, fp16 half2-packed, dense:
// [b][tap][o][32 words]  (word ip = channels 2ip, 2ip+1)
__device__ unsigned g_wmodh[NB * 9 * 64 * 32];
// style vector (sty + 1), [b][64]
__device__ float g_sty[NB * 64];

// ---------------------------------------------------------------------------
// Kernel 1a: style MLP -> g_sty (tiny)
// ---------------------------------------------------------------------------
__global__ void mlp_kernel(const float* __restrict__ vec,
                           const float* __restrict__ w1,
                           const float* __restrict__ w2) {
    const int b = blockIdx.x, tid = threadIdx.x;
    __shared__ float sv[CIN], sh[CHID];
    sv[tid] = vec[b*CIN + tid];
    __syncthreads();
    if (tid < CHID) {
        float acc = 0.f;
        #pragma unroll 8
        for (int c = 0; c < CIN; ++c) acc += sv[c] * w1[tid*CIN + c];
        sh[tid] = (acc > 0.f) ? acc : 0.1f * acc;      // LeakyReLU(0.1)
    }
    __syncthreads();
    if (tid < 64) {
        float acc = 0.f;
        #pragma unroll
        for (int j = 0; j < CHID; ++j) acc += sh[j] * w2[tid*CHID + j];
        g_sty[b*64 + tid] = acc + 1.0f;                // sty + 1
    }
}

// ---------------------------------------------------------------------------
// Kernel 1b: weight modulation + demodulation, one block per (o, b).
// ---------------------------------------------------------------------------
__global__ __launch_bounds__(64)
void demod_kernel(const float* __restrict__ wconv) {
    const int o = blockIdx.x, b = blockIdx.y, tid = threadIdx.x;
    __shared__ float ssty[64];
    __shared__ float red[2];
    __shared__ float sd;
    ssty[tid] = g_sty[b*64 + tid];
    __syncthreads();

    const float* wo = wconv + o * 576;
    float acc = 0.f;
    float wv[9];
    #pragma unroll
    for (int k = 0; k < 9; ++k) {
        const int idx = k*64 + tid;                    // idx = i*9 + t
        wv[k] = wo[idx] * ssty[idx / 9];
        acc += wv[k] * wv[k];
    }
    #pragma unroll
    for (int s = 16; s; s >>= 1) acc += __shfl_xor_sync(0xffffffffu, acc, s);
    if ((tid & 31) == 0) red[tid >> 5] = acc;
    __syncthreads();
    if (tid == 0) sd = rsqrtf(red[0] + red[1] + 1e-8f);
    __syncthreads();
    const float d = sd;

    // write packed half2: g_wmodh[((b*9+t)*64+o)*32 + ip], ip = i>>1
    for (int m = tid; m < 288; m += 64) {
        const int ip = m / 9, t = m % 9;
        const int i0 = 2 * ip;
        const float v0 = wo[i0*9 + t]     * ssty[i0]   * d;
        const float v1 = wo[(i0+1)*9 + t] * ssty[i0+1] * d;
        __half2 h = __floats2half2_rn(v0, v1);
        g_wmodh[(size_t)((b*9 + t)*64 + o)*32 + ip] = *(unsigned*)&h;
    }
}

// ---------------------------------------------------------------------------
// Kernel 2: fused ChanNorm + modulated 3x3 conv (fp16 m16n8k16, ldmatrix) + res
// (exact R5 kernel — best measured configuration)
// CTA tile: 8 rows x 32 cols x 64 out-ch.  8 warps, warp = one output row.
// xs: [pix = r*34+cc][44 words] half2; wt: double-buffered [2][64][44 words].
// ---------------------------------------------------------------------------
#define XW 44
#define NPX 340                          /* 10 halo rows * 34 halo cols */
#define OFF_WT (NPX*XW)                  /* 14960 words */
#define WTBUF  (64*XW)                   /* 2816 words per buffer */
#define OFF_G  (OFF_WT + 2*WTBUF)
#define OFF_B  (OFF_G + 64)
#define SMEM_WORDS (OFF_B + 64)          /* 20720 words = 82880 B */

__device__ __forceinline__ uint32_t smem_u32(const void* p) {
    uint32_t a;
    asm("{ .reg .u64 t; cvta.to.shared.u64 t, %1; cvt.u32.u64 %0, t; }" : "=r"(a) : "l"(p));
    return a;
}
__device__ __forceinline__ void ldsm_x4(unsigned r[4], uint32_t addr) {
    asm volatile("ldmatrix.sync.aligned.m8n8.x4.shared.b16 {%0,%1,%2,%3}, [%4];"
        : "=r"(r[0]), "=r"(r[1]), "=r"(r[2]), "=r"(r[3]) : "r"(addr));
}
__device__ __forceinline__ void mma_f16(float c[4],
                                        unsigned a0, unsigned a1,
                                        unsigned a2, unsigned a3,
                                        unsigned b0, unsigned b1) {
    asm volatile(
        "mma.sync.aligned.m16n8k16.row.col.f32.f16.f16.f32 "
        "{%0,%1,%2,%3}, {%4,%5,%6,%7}, {%8,%9}, {%0,%1,%2,%3};\n"
        : "+f"(c[0]), "+f"(c[1]), "+f"(c[2]), "+f"(c[3])
        : "r"(a0), "r"(a1), "r"(a2), "r"(a3), "r"(b0), "r"(b1));
}

__global__ __launch_bounds__(256, 2)
void conv_kernel(const float* __restrict__ x,
                 const float* __restrict__ gaff,
                 const float* __restrict__ baff,
                 float* __restrict__ out) {
    extern __shared__ unsigned sm[];
    unsigned* xs = sm;
    float* sg = (float*)(sm + OFF_G);
    float* sb = (float*)(sm + OFF_B);

    const int tid = threadIdx.x, warp = tid >> 5, lane = tid & 31;
    const int gq = lane >> 2, tq = lane & 3;
    const int x0 = blockIdx.x * 32, y0 = blockIdx.y * 8, b = blockIdx.z;
    const float* xb = x + (size_t)b * 64 * PLANE;

    if (tid < 64) { sg[tid] = gaff[tid]; sb[tid] = baff[tid]; }
    __syncthreads();

    // ---- ChanNorm halo tile -> fp16 half2 smem ----
    for (int p = tid; p < NPX; p += 256) {
        const int r = p / 34, cc = p % 34;
        const int gy = y0 - 1 + r, gx = x0 - 1 + cc;
        unsigned* dst = xs + p * XW;
        if (gy >= 0 && gy < HH && gx >= 0 && gx < WW) {
            const float* px = xb + (size_t)gy * WW + gx;
            float v[64], s = 0.f, s2 = 0.f;
            #pragma unroll
            for (int c = 0; c < 64; ++c) v[c] = px[(size_t)c * PLANE];
            #pragma unroll
            for (int c = 0; c < 64; ++c) { s += v[c]; s2 += v[c]*v[c]; }
            const float mean = s * (1.f/64.f);
            const float rstd = rsqrtf(s2 * (1.f/64.f) - mean*mean + 1e-5f);
            #pragma unroll
            for (int w = 0; w < 32; ++w) {
                float n0 = (v[2*w]   - mean) * rstd * sg[2*w]   + sb[2*w];
                float n1 = (v[2*w+1] - mean) * rstd * sg[2*w+1] + sb[2*w+1];
                __half2 h = __floats2half2_rn(n0, n1);
                dst[w] = *(unsigned*)&h;
            }
        } else {
            #pragma unroll
            for (int w = 0; w < 32; ++w) dst[w] = 0u;   // pad AFTER norm
        }
    }

    // ---- weight prefetch machinery ----
    const unsigned* wbase = g_wmodh + (size_t)(b * 9) * 2048;
    const int wo = tid >> 2, ww0 = (tid & 3) * 8;      // wt STS mapping
    unsigned wr[8];
    {   // tap 0 -> regs
        const uint4* s4 = (const uint4*)wbase + tid * 2;
        uint4 u0 = s4[0], u1 = s4[1];
        wr[0]=u0.x; wr[1]=u0.y; wr[2]=u0.z; wr[3]=u0.w;
        wr[4]=u1.x; wr[5]=u1.y; wr[6]=u1.z; wr[7]=u1.w;
    }
    {   // tap 0 -> wt buffer 0
        unsigned* d = sm + OFF_WT + wo * XW + ww0;
        #pragma unroll
        for (int i = 0; i < 8; ++i) d[i] = wr[i];
    }
    {   // tap 1 -> regs
        const uint4* s4 = (const uint4*)(wbase + 2048) + tid * 2;
        uint4 u0 = s4[0], u1 = s4[1];
        wr[0]=u0.x; wr[1]=u0.y; wr[2]=u0.z; wr[3]=u0.w;
        wr[4]=u1.x; wr[5]=u1.y; wr[6]=u1.z; wr[7]=u1.w;
    }

    // ---- ldmatrix base addresses (byte, shared space) ----
    const uint32_t xs_sa = smem_u32(sm);
    const uint32_t wt_sa = xs_sa + OFF_WT * 4;
    const uint32_t A0 = xs_sa + ((warp * 34 + (lane & 15)) * XW) * 4 + (lane >> 4) * 16;
    const uint32_t B0 = wt_sa + (((lane & 7) + ((lane >> 4) & 1) * 8) * XW) * 4
                              + ((lane >> 3) & 1) * 16;

    __syncthreads();                                   // xs + wt0 ready

    float acc[2][8][4];
    #pragma unroll
    for (int mt = 0; mt < 2; ++mt)
        #pragma unroll
        for (int nt = 0; nt < 8; ++nt)
            #pragma unroll
            for (int j = 0; j < 4; ++j) acc[mt][nt][j] = 0.f;

    for (int j = 0; j < 9; ++j) {
        const int ky = j / 3, kx = j % 3, s = j & 1;
        const uint32_t Abase = A0 + (uint32_t)((ky * 34 + kx) * XW) * 4;
        const uint32_t Bbase = B0 + (uint32_t)(s * WTBUF) * 4;

        #pragma unroll
        for (int kt = 0; kt < 4; ++kt) {
            const uint32_t ko = (uint32_t)kt * 32;
            unsigned a[2][4], bq[4][4];
            ldsm_x4(a[0], Abase + ko);
            ldsm_x4(a[1], Abase + ko + 16 * XW * 4);
            #pragma unroll
            for (int q = 0; q < 4; ++q)
                ldsm_x4(bq[q], Bbase + ko + (uint32_t)(q * 16 * XW) * 4);
            #pragma unroll
            for (int mt = 0; mt < 2; ++mt) {
                #pragma unroll
                for (int q = 0; q < 4; ++q) {
                    mma_f16(acc[mt][2*q],   a[mt][0], a[mt][1], a[mt][2], a[mt][3],
                            bq[q][0], bq[q][1]);
                    mma_f16(acc[mt][2*q+1], a[mt][0], a[mt][1], a[mt][2], a[mt][3],
                            bq[q][2], bq[q][3]);
                }
            }
        }

        if (j < 8) {
            unsigned* d = sm + OFF_WT + (s ^ 1) * WTBUF + wo * XW + ww0;
            #pragma unroll
            for (int i = 0; i < 8; ++i) d[i] = wr[i];
            if (j < 7) {
                const uint4* s4 = (const uint4*)(wbase + (size_t)(j+2)*2048) + tid*2;
                uint4 u0 = s4[0], u1 = s4[1];
                wr[0]=u0.x; wr[1]=u0.y; wr[2]=u0.z; wr[3]=u0.w;
                wr[4]=u1.x; wr[5]=u1.y; wr[6]=u1.z; wr[7]=u1.w;
            }
        }
        __syncthreads();
    }

    // ---- epilogue: residual add + store ----
    const int gy = y0 + warp;
    float* ob = out + (size_t)b * 64 * PLANE;
    #pragma unroll
    for (int mt = 0; mt < 2; ++mt) {
        const int px = x0 + mt*16 + gq;
        #pragma unroll
        for (int nt = 0; nt < 8; ++nt) {
            const int c0 = nt*8 + 2*tq;
            const size_t i00 = (size_t)c0 * PLANE + (size_t)gy * WW + px;
            ob[i00]             = xb[i00]             + acc[mt][nt][0];
            ob[i00 + PLANE]     = xb[i00 + PLANE]     + acc[mt][nt][1];
            ob[i00 + 8]         = xb[i00 + 8]         + acc[mt][nt][2];
            ob[i00 + PLANE + 8] = xb[i00 + PLANE + 8] + acc[mt][nt][3];
        }
    }
}

// ---------------------------------------------------------------------------
extern "C" void kernel_launch(void* const* d_in, const int* in_sizes, int n_in,
                              void* d_out, int out_size) {
    (void)in_sizes; (void)n_in; (void)out_size;
    const float* x     = (const float*)d_in[0];
    const float* vec   = (const float*)d_in[1];
    const float* gaff  = (const float*)d_in[2];
    const float* baff  = (const float*)d_in[3];
    const float* w1    = (const float*)d_in[4];
    const float* w2    = (const float*)d_in[5];
    const float* wconv = (const float*)d_in[6];
    float* out = (float*)d_out;

    mlp_kernel<<<NB, 256>>>(vec, w1, w2);
    dim3 dgrid(64, NB);
    demod_kernel<<<dgrid, 64>>>(wconv);

    const int smem = SMEM_WORDS * 4;
    cudaFuncSetAttribute(conv_kernel,
                         cudaFuncAttributeMaxDynamicSharedMemorySize, smem);
    dim3 grid(WW/32, HH/8, NB);
    conv_kernel<<<grid, 256, smem>>>(x, gaff, baff, out);
}

// round 9
// speedup vs baseline: 1.6861x; 1.1094x over previous
#include <cuda_runtime.h>
#include <cuda_fp16.h>
#include <cstdint>

#define HH 256
#define WW 256
#define NB 8
#define PLANE (HH*WW)
#define CIN 256
#define CHID 16

// per-sample demodulated conv weights, fp16 half2-packed, dense:
// [b][tap][o][32 words]  (word ip = channels 2ip, 2ip+1)
__device__ unsigned g_wmodh[NB * 9 * 64 * 32];
// style vector (sty + 1), [b][64]
__device__ float g_sty[NB * 64];

// ---------------------------------------------------------------------------
// Kernel 1a: style MLP -> g_sty.  All 256 threads on the w1 GEMV:
// warp w handles hid = 2w + (lane>>4); 16 lanes x 16-elem chunks, shfl-reduce.
// ---------------------------------------------------------------------------
__global__ void mlp_kernel(const float* __restrict__ vec,
                           const float* __restrict__ w1,
                           const float* __restrict__ w2) {
    const int b = blockIdx.x, tid = threadIdx.x;
    const int warp = tid >> 5, lane = tid & 31;
    __shared__ float sv[CIN], sh[CHID];
    sv[tid] = vec[b*CIN + tid];
    __syncthreads();

    {
        const int h = 2*warp + (lane >> 4);
        const int c0 = (lane & 15) * 16;
        const float* wrow = w1 + h*CIN + c0;
        float acc = 0.f;
        #pragma unroll
        for (int i = 0; i < 16; ++i) acc += sv[c0 + i] * wrow[i];
        #pragma unroll
        for (int s = 8; s; s >>= 1)
            acc += __shfl_xor_sync(0xffffffffu, acc, s);
        if ((lane & 15) == 0)
            sh[h] = (acc > 0.f) ? acc : 0.1f * acc;    // LeakyReLU(0.1)
    }
    __syncthreads();
    if (tid < 64) {
        float acc = 0.f;
        #pragma unroll
        for (int j = 0; j < CHID; ++j) acc += sh[j] * w2[tid*CHID + j];
        g_sty[b*64 + tid] = acc + 1.0f;                // sty + 1
    }
}

// ---------------------------------------------------------------------------
// Kernel 1b: weight modulation + demodulation, one block per (o, b).
// ---------------------------------------------------------------------------
__global__ __launch_bounds__(64)
void demod_kernel(const float* __restrict__ wconv) {
    const int o = blockIdx.x, b = blockIdx.y, tid = threadIdx.x;
    __shared__ float ssty[64];
    __shared__ float red[2];
    __shared__ float sd;
    ssty[tid] = g_sty[b*64 + tid];
    __syncthreads();

    const float* wo = wconv + o * 576;
    float acc = 0.f;
    float wv[9];
    #pragma unroll
    for (int k = 0; k < 9; ++k) {
        const int idx = k*64 + tid;                    // idx = i*9 + t
        wv[k] = wo[idx] * ssty[idx / 9];
        acc += wv[k] * wv[k];
    }
    #pragma unroll
    for (int s = 16; s; s >>= 1) acc += __shfl_xor_sync(0xffffffffu, acc, s);
    if ((tid & 31) == 0) red[tid >> 5] = acc;
    __syncthreads();
    if (tid == 0) sd = rsqrtf(red[0] + red[1] + 1e-8f);
    __syncthreads();
    const float d = sd;

    for (int m = tid; m < 288; m += 64) {
        const int ip = m / 9, t = m % 9;
        const int i0 = 2 * ip;
        const float v0 = wo[i0*9 + t]     * ssty[i0]   * d;
        const float v1 = wo[(i0+1)*9 + t] * ssty[i0+1] * d;
        __half2 h = __floats2half2_rn(v0, v1);
        g_wmodh[(size_t)((b*9 + t)*64 + o)*32 + ip] = *(unsigned*)&h;
    }
}

// ---------------------------------------------------------------------------
// Kernel 2: fused ChanNorm + modulated 3x3 conv (fp16 m16n8k16, ldmatrix) + res
// (R5 MMA structure; NEW smem-staged coalesced epilogue)
// CTA tile: 8 rows x 32 cols x 64 out-ch.  8 warps, warp = one output row.
// xs: [pix = r*34+cc][44 words] half2; wt: double-buffered [2][64][44 words].
// ---------------------------------------------------------------------------
#define XW 44
#define NPX 340                          /* 10 halo rows * 34 halo cols */
#define OFF_WT (NPX*XW)                  /* 14960 words */
#define WTBUF  (64*XW)                   /* 2816 words per buffer */
#define OFF_G  (OFF_WT + 2*WTBUF)
#define OFF_B  (OFF_G + 64)
#define SMEM_WORDS (OFF_B + 64)          /* 20720 words = 82880 B */

__device__ __forceinline__ uint32_t smem_u32(const void* p) {
    uint32_t a;
    asm("{ .reg .u64 t; cvta.to.shared.u64 t, %1; cvt.u32.u64 %0, t; }" : "=r"(a) : "l"(p));
    return a;
}
__device__ __forceinline__ void ldsm_x4(unsigned r[4], uint32_t addr) {
    asm volatile("ldmatrix.sync.aligned.m8n8.x4.shared.b16 {%0,%1,%2,%3}, [%4];"
        : "=r"(r[0]), "=r"(r[1]), "=r"(r[2]), "=r"(r[3]) : "r"(addr));
}
__device__ __forceinline__ void mma_f16(float c[4],
                                        unsigned a0, unsigned a1,
                                        unsigned a2, unsigned a3,
                                        unsigned b0, unsigned b1) {
    asm volatile(
        "mma.sync.aligned.m16n8k16.row.col.f32.f16.f16.f32 "
        "{%0,%1,%2,%3}, {%4,%5,%6,%7}, {%8,%9}, {%0,%1,%2,%3};\n"
        : "+f"(c[0]), "+f"(c[1]), "+f"(c[2]), "+f"(c[3])
        : "r"(a0), "r"(a1), "r"(a2), "r"(a3), "r"(b0), "r"(b1));
}

__global__ __launch_bounds__(256, 2)
void conv_kernel(const float* __restrict__ x,
                 const float* __restrict__ gaff,
                 const float* __restrict__ baff,
                 float* __restrict__ out) {
    extern __shared__ unsigned sm[];
    unsigned* xs = sm;
    float* sg = (float*)(sm + OFF_G);
    float* sb = (float*)(sm + OFF_B);

    const int tid = threadIdx.x, warp = tid >> 5, lane = tid & 31;
    const int gq = lane >> 2, tq = lane & 3;
    const int x0 = blockIdx.x * 32, y0 = blockIdx.y * 8, b = blockIdx.z;
    const float* xb = x + (size_t)b * 64 * PLANE;

    if (tid < 64) { sg[tid] = gaff[tid]; sb[tid] = baff[tid]; }
    __syncthreads();

    // ---- ChanNorm halo tile -> fp16 half2 smem ----
    for (int p = tid; p < NPX; p += 256) {
        const int r = p / 34, cc = p % 34;
        const int gy = y0 - 1 + r, gx = x0 - 1 + cc;
        unsigned* dst = xs + p * XW;
        if (gy >= 0 && gy < HH && gx >= 0 && gx < WW) {
            const float* px = xb + (size_t)gy * WW + gx;
            float v[64], s = 0.f, s2 = 0.f;
            #pragma unroll
            for (int c = 0; c < 64; ++c) v[c] = px[(size_t)c * PLANE];
            #pragma unroll
            for (int c = 0; c < 64; ++c) { s += v[c]; s2 += v[c]*v[c]; }
            const float mean = s * (1.f/64.f);
            const float rstd = rsqrtf(s2 * (1.f/64.f) - mean*mean + 1e-5f);
            #pragma unroll
            for (int w = 0; w < 32; ++w) {
                float n0 = (v[2*w]   - mean) * rstd * sg[2*w]   + sb[2*w];
                float n1 = (v[2*w+1] - mean) * rstd * sg[2*w+1] + sb[2*w+1];
                __half2 h = __floats2half2_rn(n0, n1);
                dst[w] = *(unsigned*)&h;
            }
        } else {
            #pragma unroll
            for (int w = 0; w < 32; ++w) dst[w] = 0u;   // pad AFTER norm
        }
    }

    // ---- weight prefetch machinery ----
    const unsigned* wbase = g_wmodh + (size_t)(b * 9) * 2048;
    const int wo = tid >> 2, ww0 = (tid & 3) * 8;      // wt STS mapping
    unsigned wr[8];
    {   // tap 0 -> regs
        const uint4* s4 = (const uint4*)wbase + tid * 2;
        uint4 u0 = s4[0], u1 = s4[1];
        wr[0]=u0.x; wr[1]=u0.y; wr[2]=u0.z; wr[3]=u0.w;
        wr[4]=u1.x; wr[5]=u1.y; wr[6]=u1.z; wr[7]=u1.w;
    }
    {   // tap 0 -> wt buffer 0
        unsigned* d = sm + OFF_WT + wo * XW + ww0;
        #pragma unroll
        for (int i = 0; i < 8; ++i) d[i] = wr[i];
    }
    {   // tap 1 -> regs
        const uint4* s4 = (const uint4*)(wbase + 2048) + tid * 2;
        uint4 u0 = s4[0], u1 = s4[1];
        wr[0]=u0.x; wr[1]=u0.y; wr[2]=u0.z; wr[3]=u0.w;
        wr[4]=u1.x; wr[5]=u1.y; wr[6]=u1.z; wr[7]=u1.w;
    }

    // ---- ldmatrix base addresses (byte, shared space) ----
    const uint32_t xs_sa = smem_u32(sm);
    const uint32_t wt_sa = xs_sa + OFF_WT * 4;
    const uint32_t A0 = xs_sa + ((warp * 34 + (lane & 15)) * XW) * 4 + (lane >> 4) * 16;
    const uint32_t B0 = wt_sa + (((lane & 7) + ((lane >> 4) & 1) * 8) * XW) * 4
                              + ((lane >> 3) & 1) * 16;

    __syncthreads();                                   // xs + wt0 ready

    float acc[2][8][4];
    #pragma unroll
    for (int mt = 0; mt < 2; ++mt)
        #pragma unroll
        for (int nt = 0; nt < 8; ++nt)
            #pragma unroll
            for (int j = 0; j < 4; ++j) acc[mt][nt][j] = 0.f;

    for (int j = 0; j < 9; ++j) {
        const int ky = j / 3, kx = j % 3, s = j & 1;
        const uint32_t Abase = A0 + (uint32_t)((ky * 34 + kx) * XW) * 4;
        const uint32_t Bbase = B0 + (uint32_t)(s * WTBUF) * 4;

        #pragma unroll
        for (int kt = 0; kt < 4; ++kt) {
            const uint32_t ko = (uint32_t)kt * 32;
            unsigned a[2][4], bq[4][4];
            ldsm_x4(a[0], Abase + ko);
            ldsm_x4(a[1], Abase + ko + 16 * XW * 4);
            #pragma unroll
            for (int q = 0; q < 4; ++q)
                ldsm_x4(bq[q], Bbase + ko + (uint32_t)(q * 16 * XW) * 4);
            #pragma unroll
            for (int mt = 0; mt < 2; ++mt) {
                #pragma unroll
                for (int q = 0; q < 4; ++q) {
                    mma_f16(acc[mt][2*q],   a[mt][0], a[mt][1], a[mt][2], a[mt][3],
                            bq[q][0], bq[q][1]);
                    mma_f16(acc[mt][2*q+1], a[mt][0], a[mt][1], a[mt][2], a[mt][3],
                            bq[q][2], bq[q][3]);
                }
            }
        }

        if (j < 8) {
            unsigned* d = sm + OFF_WT + (s ^ 1) * WTBUF + wo * XW + ww0;
            #pragma unroll
            for (int i = 0; i < 8; ++i) d[i] = wr[i];
            if (j < 7) {
                const uint4* s4 = (const uint4*)(wbase + (size_t)(j+2)*2048) + tid*2;
                uint4 u0 = s4[0], u1 = s4[1];
                wr[0]=u0.x; wr[1]=u0.y; wr[2]=u0.z; wr[3]=u0.w;
                wr[4]=u1.x; wr[5]=u1.y; wr[6]=u1.z; wr[7]=u1.w;
            }
        }
        __syncthreads();
    }

    // ---- epilogue: stage acc -> smem [ch][36] (conflict-free), coalesced I/O ----
    __syncthreads();                          // all LDSM reads of xs/wt done
    float* ss = (float*)sm + warp * 2304;     // 64 ch x 36 floats per warp
    const int gy = y0 + warp;
    float* ob = out + (size_t)b * 64 * PLANE;

    #pragma unroll
    for (int mt = 0; mt < 2; ++mt) {
        const int px = mt*16 + gq;
        #pragma unroll
        for (int nt = 0; nt < 8; ++nt) {
            const int c0 = nt*8 + 2*tq;
            ss[c0*36 + px]         = acc[mt][nt][0];
            ss[(c0+1)*36 + px]     = acc[mt][nt][1];
            ss[c0*36 + px + 8]     = acc[mt][nt][2];
            ss[(c0+1)*36 + px + 8] = acc[mt][nt][3];
        }
    }
    __syncwarp();
    const size_t gbase = (size_t)gy * WW + x0 + lane;
    #pragma unroll 8
    for (int c = 0; c < 64; ++c) {
        const size_t gi = (size_t)c * PLANE + gbase;
        ob[gi] = xb[gi] + ss[c*36 + lane];
    }
}

// ---------------------------------------------------------------------------
extern "C" void kernel_launch(void* const* d_in, const int* in_sizes, int n_in,
                              void* d_out, int out_size) {
    (void)in_sizes; (void)n_in; (void)out_size;
    const float* x     = (const float*)d_in[0];
    const float* vec   = (const float*)d_in[1];
    const float* gaff  = (const float*)d_in[2];
    const float* baff  = (const float*)d_in[3];
    const float* w1    = (const float*)d_in[4];
    const float* w2    = (const float*)d_in[5];
    const float* wconv = (const float*)d_in[6];
    float* out = (float*)d_out;

    mlp_kernel<<<NB, 256>>>(vec, w1, w2);
    dim3 dgrid(64, NB);
    demod_kernel<<<dgrid, 64>>>(wconv);

    const int smem = SMEM_WORDS * 4;
    cudaFuncSetAttribute(conv_kernel,
                         cudaFuncAttributeMaxDynamicSharedMemorySize, smem);
    dim3 grid(WW/32, HH/8, NB);
    conv_kernel<<<grid, 256, smem>>>(x, gaff, baff, out);
}